// round 12
// baseline (speedup 1.0000x reference)
#include <cuda_runtime.h>
#include <cuda_bf16.h>
#include <stdint.h>

#define Bsz 16384
#define Dd 512
#define Hh 256
#define Rr 95

// ------------------------------- scratch -----------------------------------
__device__ uint32_t g_acth[2][Bsz][Hh / 2];   // post-GELU acts, bf16x2 hi
__device__ uint32_t g_actl[2][Bsz][Hh / 2];   // post-GELU acts, bf16x2 lo
__device__ float    g_m[2][Bsz][64];          // mp / mv multivectors
__device__ uint32_t g_W1s[2][2][Dd / 2][Hh];  // [side][hi/lo][k2][n]
__device__ uint32_t g_W2s[2][2][Hh / 2][64];
__device__ uint32_t g_Qh[Bsz][32];            // Q collapsed, bf16x2 hi (k2)
__device__ uint32_t g_Ql[Bsz][32];
__device__ uint32_t g_Th[32][128];            // T*0.125 pre-split [k2][n(pad 128)]
__device__ uint32_t g_Tl[32][128];

// ------------------------------- helpers -----------------------------------
__device__ __forceinline__ float gelu_exact(float x) {
    return 0.5f * x * (1.0f + erff(x * 0.70710678118654752440f));
}
__device__ __forceinline__ float csign(int a, int b) {
    int sw = __popc((a >> 1) & b) + __popc((a >> 2) & b);
    return (sw & 1) ? -1.0f : 1.0f;
}
__device__ __forceinline__ int cidx(int m) { return m + (m == 3) - (m == 4); }

__device__ __forceinline__ void bf16_split_pack(float x0, float x1,
                                                uint32_t& hp, uint32_t& lp) {
    __nv_bfloat16 h0 = __float2bfloat16(x0), h1 = __float2bfloat16(x1);
    float r0 = x0 - __bfloat162float(h0);
    float r1 = x1 - __bfloat162float(h1);
    __nv_bfloat16 l0 = __float2bfloat16(r0), l1 = __float2bfloat16(r1);
    hp = ((uint32_t)__bfloat16_as_ushort(h1) << 16) | (uint32_t)__bfloat16_as_ushort(h0);
    lp = ((uint32_t)__bfloat16_as_ushort(l1) << 16) | (uint32_t)__bfloat16_as_ushort(l0);
}

#define MMA_BF16(d, a, b) \
    asm volatile("mma.sync.aligned.m16n8k16.row.col.f32.bf16.bf16.f32 " \
        "{%0,%1,%2,%3}, {%4,%5,%6,%7}, {%8,%9}, {%0,%1,%2,%3};" \
        : "+f"(d[0]), "+f"(d[1]), "+f"(d[2]), "+f"(d[3]) \
        : "r"(a[0]), "r"(a[1]), "r"(a[2]), "r"(a[3]), "r"(b[0]), "r"(b[1]))

__device__ __forceinline__ void cp16(uint32_t saddr, const void* g) {
    asm volatile("cp.async.cg.shared.global [%0], [%1], 16;" :: "r"(saddr), "l"(g));
}
#define CP_COMMIT() asm volatile("cp.async.commit_group;" ::: "memory")
#define CP_WAIT0()  asm volatile("cp.async.wait_group 0;"  ::: "memory")

// ---------------------------------------------------------------------------
// prep (merged): W1 split, W2 split, T split (pre-scaled 1/8)
// ---------------------------------------------------------------------------
#define N_W1 (2 * (Dd / 2) * Hh)          // 131072 (65536 = 2^16 per side)
#define N_W2 (2 * (Hh / 2) * 64)          // 16384  (8192  = 2^13 per side)
#define N_T  (32 * 128)                   // 4096
__global__ __launch_bounds__(256) void k_prep(
    const float* __restrict__ W1p, const float* __restrict__ W1v,
    const float* __restrict__ W2p, const float* __restrict__ W2v,
    const float* __restrict__ T)
{
    int idx = blockIdx.x * 256 + threadIdx.x;
    if (idx < N_W1) {
        int side = idx >> 16;
        int rem  = idx & 0xFFFF;
        int k2   = rem >> 8;
        int n    = rem & 255;
        const float* W = side ? W1v : W1p;
        float x0 = __ldg(&W[(2 * k2) * Hh + n]);
        float x1 = __ldg(&W[(2 * k2 + 1) * Hh + n]);
        uint32_t hp, lp;
        bf16_split_pack(x0, x1, hp, lp);
        g_W1s[side][0][k2][n] = hp;
        g_W1s[side][1][k2][n] = lp;
    } else if (idx < N_W1 + N_W2) {
        int j = idx - N_W1;
        int side = j >> 13;               // 8192 = 2^13 elements per side
        int rem  = j & 0x1FFF;
        int k2   = rem >> 6;              // 0..127
        int n    = rem & 63;
        const float* W = side ? W2v : W2p;
        float x0 = __ldg(&W[(2 * k2) * 64 + n]);
        float x1 = __ldg(&W[(2 * k2 + 1) * 64 + n]);
        uint32_t hp, lp;
        bf16_split_pack(x0, x1, hp, lp);
        g_W2s[side][0][k2][n] = hp;
        g_W2s[side][1][k2][n] = lp;
    } else if (idx < N_W1 + N_W2 + N_T) {
        int j = idx - N_W1 - N_W2;
        int k2 = j >> 7;
        int n  = j & 127;
        float x0 = 0.0f, x1 = 0.0f;
        if (n < Rr) {
            x0 = __ldg(&T[n * 64 + 2 * k2])     * 0.125f;
            x1 = __ldg(&T[n * 64 + 2 * k2 + 1]) * 0.125f;
        }
        uint32_t hp, lp;
        bf16_split_pack(x0, x1, hp, lp);
        g_Th[k2][n] = hp;
        g_Tl[k2][n] = lp;
    }
}

// ---------------------------------------------------------------------------
// GEMM1 fused + double-buffered, 512 threads (16 warps, 4/SMSP):
// Y = X@W1+b1 -> LN -> GELU. BM=64, BN=256, BK=16. Warp tile 64x16.
// Stage word layout: Ah [0,576) Al [576,1152) Bh [1152,3264) Bl [3264,5376)
// 2 stages x 21504 B = 43008 B static; epilogue s_part/s_ln alias stage mem.
// ---------------------------------------------------------------------------
#define STG_W 5376

__device__ __forceinline__ void stsA(uint32_t* __restrict__ dsm, int so,
                                     float4 a, int tid) {
    int row = tid >> 2, k2 = (tid & 3) * 2;
    uint32_t hp0, lp0, hp1, lp1;
    bf16_split_pack(a.x, a.y, hp0, lp0);
    bf16_split_pack(a.z, a.w, hp1, lp1);
    dsm[so + k2 * 72 + row]              = hp0;
    dsm[so + (k2 + 1) * 72 + row]        = hp1;
    dsm[so + 576 + k2 * 72 + row]        = lp0;
    dsm[so + 576 + (k2 + 1) * 72 + row]  = lp1;
}

// 512 threads: each does one hi and one lo cp16
__device__ __forceinline__ void cpB(uint32_t sdyn, int so, int side,
                                    int k2base, int tid) {
    int k2l = tid >> 6, n4 = (tid & 63) * 4;
    cp16(sdyn + (uint32_t)(so + 1152 + k2l * 264 + n4) * 4,
         &g_W1s[side][0][k2base + k2l][n4]);
    cp16(sdyn + (uint32_t)(so + 3264 + k2l * 264 + n4) * 4,
         &g_W1s[side][1][k2base + k2l][n4]);
}

__global__ __launch_bounds__(512) void k_gemm1f(
    const float* __restrict__ Xp, const float* __restrict__ Xv,
    const float* __restrict__ b1p, const float* __restrict__ b1v,
    const float* __restrict__ lgp, const float* __restrict__ lgv,
    const float* __restrict__ lbp, const float* __restrict__ lbv)
{
    __shared__ uint32_t dsm[2 * STG_W];

    const int side = blockIdx.y;
    const float* __restrict__ X  = side ? Xv : Xp;
    const float* __restrict__ b1 = side ? b1v : b1p;
    const float* __restrict__ lg = side ? lgv : lgp;
    const float* __restrict__ lb = side ? lbv : lbp;

    const int tid  = threadIdx.x;
    const int lane = tid & 31;
    const int wid  = tid >> 5;        // 0..15
    const int gid  = lane >> 2;
    const int tig  = lane & 3;
    const int wc0  = wid * 16;        // warp col base (16 cols per warp)
    const int row0 = blockIdx.x * 64;
    const uint32_t sdyn = (uint32_t)__cvta_generic_to_shared(dsm);

    float acc[4][2][4];
    #pragma unroll
    for (int mt = 0; mt < 4; mt++)
        #pragma unroll
        for (int nt = 0; nt < 2; nt++)
            #pragma unroll
            for (int e = 0; e < 4; e++) acc[mt][nt][e] = 0.0f;

    const bool aldr = (tid < 256);
    const int arow = row0 + ((tid & 255) >> 2);
    const int acol = (tid & 3) * 4;

    float4 areg = make_float4(0.f, 0.f, 0.f, 0.f);
    // ---- prologue: stage 0 ----
    if (aldr) areg = *reinterpret_cast<const float4*>(&X[arow * Dd + acol]);
    if (aldr) stsA(dsm, 0, areg, tid);
    cpB(sdyn, 0, side, 0, tid);
    CP_COMMIT();
    if (aldr) areg = *reinterpret_cast<const float4*>(&X[arow * Dd + 16 + acol]);
    CP_WAIT0();
    __syncthreads();

    #pragma unroll 1
    for (int kt = 0; kt < 32; kt++) {
        const int cur = (kt & 1) * STG_W;
        const int nxt = ((kt & 1) ^ 1) * STG_W;

        if (kt < 31) {
            if (aldr) stsA(dsm, nxt, areg, tid);     // A(kt+1) -> next stage
            cpB(sdyn, nxt, side, (kt + 1) * 8, tid);
            CP_COMMIT();
            if (kt < 30 && aldr) {
                int kn = (kt + 2) * 16;
                areg = *reinterpret_cast<const float4*>(&X[arow * Dd + kn + acol]);
            }
        }

        {
            uint32_t ah[4][4], al[4][4], bh[2][2], bl[2][2];
            #pragma unroll
            for (int mt = 0; mt < 4; mt++) {
                int r = mt * 16 + gid;
                ah[mt][0] = dsm[cur + tig * 72 + r];
                ah[mt][1] = dsm[cur + tig * 72 + r + 8];
                ah[mt][2] = dsm[cur + (tig + 4) * 72 + r];
                ah[mt][3] = dsm[cur + (tig + 4) * 72 + r + 8];
                al[mt][0] = dsm[cur + 576 + tig * 72 + r];
                al[mt][1] = dsm[cur + 576 + tig * 72 + r + 8];
                al[mt][2] = dsm[cur + 576 + (tig + 4) * 72 + r];
                al[mt][3] = dsm[cur + 576 + (tig + 4) * 72 + r + 8];
            }
            #pragma unroll
            for (int nt = 0; nt < 2; nt++) {
                int c = wc0 + nt * 8 + gid;
                bh[nt][0] = dsm[cur + 1152 + tig * 264 + c];
                bh[nt][1] = dsm[cur + 1152 + (tig + 4) * 264 + c];
                bl[nt][0] = dsm[cur + 3264 + tig * 264 + c];
                bl[nt][1] = dsm[cur + 3264 + (tig + 4) * 264 + c];
            }
            #pragma unroll
            for (int mt = 0; mt < 4; mt++)
                #pragma unroll
                for (int nt = 0; nt < 2; nt++) {
                    MMA_BF16(acc[mt][nt], ah[mt], bh[nt]);
                    MMA_BF16(acc[mt][nt], al[mt], bh[nt]);
                    MMA_BF16(acc[mt][nt], ah[mt], bl[nt]);
                }
        }

        if (kt < 31) {
            CP_WAIT0();
            __syncthreads();
        }
    }

    // ------------- fused epilogue: bias + LayerNorm + GELU + split ----------
    float bcol[4], lgc[4], lbc[4];
    #pragma unroll
    for (int nt = 0; nt < 2; nt++) {
        int c = wc0 + nt * 8 + tig * 2;
        bcol[nt * 2] = __ldg(&b1[c]); bcol[nt * 2 + 1] = __ldg(&b1[c + 1]);
        lgc[nt * 2]  = __ldg(&lg[c]); lgc[nt * 2 + 1]  = __ldg(&lg[c + 1]);
        lbc[nt * 2]  = __ldg(&lb[c]); lbc[nt * 2 + 1]  = __ldg(&lb[c + 1]);
    }

    float s[8], s2[8];
    #pragma unroll
    for (int q = 0; q < 8; q++) { s[q] = 0.0f; s2[q] = 0.0f; }
    #pragma unroll
    for (int mt = 0; mt < 4; mt++)
        #pragma unroll
        for (int nt = 0; nt < 2; nt++)
            #pragma unroll
            for (int e = 0; e < 4; e++) {
                float v = acc[mt][nt][e] + bcol[nt * 2 + (e & 1)];
                acc[mt][nt][e] = v;
                int slot = mt * 2 + (e >> 1);
                s[slot] += v; s2[slot] += v * v;
            }
    #pragma unroll
    for (int q = 0; q < 8; q++) {
        s[q]  += __shfl_xor_sync(0xffffffffu, s[q],  1);
        s[q]  += __shfl_xor_sync(0xffffffffu, s[q],  2);
        s2[q] += __shfl_xor_sync(0xffffffffu, s2[q], 1);
        s2[q] += __shfl_xor_sync(0xffffffffu, s2[q], 2);
    }

    // epilogue scratch aliases the (now dead) pipeline buffer
    float2* s_part = reinterpret_cast<float2*>(dsm);          // [16][64]
    float2* s_ln   = reinterpret_cast<float2*>(dsm + 2048);   // [64]

    __syncthreads();   // all MMA-stage reads of dsm done before aliasing
    if (tig == 0) {
        #pragma unroll
        for (int mt = 0; mt < 4; mt++) {
            s_part[wid * 64 + mt * 16 + gid]     = make_float2(s[mt * 2],     s2[mt * 2]);
            s_part[wid * 64 + mt * 16 + 8 + gid] = make_float2(s[mt * 2 + 1], s2[mt * 2 + 1]);
        }
    }
    __syncthreads();
    if (tid < 64) {
        float ts = 0.0f, ts2 = 0.0f;
        #pragma unroll
        for (int w = 0; w < 16; w++) {
            float2 p = s_part[w * 64 + tid];
            ts += p.x; ts2 += p.y;
        }
        float mu   = ts * (1.0f / 256.0f);
        float var  = ts2 * (1.0f / 256.0f) - mu * mu;
        s_ln[tid] = make_float2(mu, rsqrtf(var + 1e-5f));
    }
    __syncthreads();

    #pragma unroll
    for (int mt = 0; mt < 4; mt++)
        #pragma unroll
        for (int h = 0; h < 2; h++) {
            int rl = mt * 16 + h * 8 + gid;
            float2 ln = s_ln[rl];
            int row = row0 + rl;
            #pragma unroll
            for (int nt = 0; nt < 2; nt++) {
                float v0 = acc[mt][nt][h * 2];
                float v1 = acc[mt][nt][h * 2 + 1];
                float y0 = gelu_exact((v0 - ln.x) * ln.y * lgc[nt * 2]     + lbc[nt * 2]);
                float y1 = gelu_exact((v1 - ln.x) * ln.y * lgc[nt * 2 + 1] + lbc[nt * 2 + 1]);
                uint32_t hp, lp;
                bf16_split_pack(y0, y1, hp, lp);
                int k2 = (wc0 >> 1) + nt * 4 + tig;
                g_acth[side][row][k2] = hp;
                g_actl[side][row][k2] = lp;
            }
        }
}

// ---------------------------------------------------------------------------
// GEMM2: M(B,64) = act(B,256) @ W2(256,64) + b2 -> g_m  (unchanged, passing)
// ---------------------------------------------------------------------------
__global__ __launch_bounds__(256, 2) void k_gemm2(
    const float* __restrict__ b2p, const float* __restrict__ b2v)
{
    const int side = blockIdx.y;
    const float* __restrict__ b2 = side ? b2v : b2p;

    __shared__ uint32_t Ah[128][20], Al[128][20], Bh[16][72], Bl[16][72];

    const int tid  = threadIdx.x;
    const int lane = tid & 31;
    const int wid  = tid >> 5;
    const int gid  = lane >> 2;
    const int tig  = lane & 3;
    const int wr0  = (wid & 3) * 32;
    const int wc0  = (wid >> 2) * 32;
    const int row0 = blockIdx.x * 128;

    float acc[2][4][4];
    #pragma unroll
    for (int mt = 0; mt < 2; mt++)
        #pragma unroll
        for (int nt = 0; nt < 4; nt++)
            #pragma unroll
            for (int e = 0; e < 4; e++) acc[mt][nt][e] = 0.0f;

    uint4 ahreg[2], alreg[2], bhreg, blreg;
    #pragma unroll
    for (int q = 0; q < 2; q++) {
        int idx = tid + q * 256;
        int row = idx >> 2, k2q = (idx & 3) * 4;
        ahreg[q] = *reinterpret_cast<const uint4*>(&g_acth[side][row0 + row][k2q]);
        alreg[q] = *reinterpret_cast<const uint4*>(&g_actl[side][row0 + row][k2q]);
    }
    {
        int k2l = tid >> 4, n4 = (tid & 15) * 4;
        bhreg = *reinterpret_cast<const uint4*>(&g_W2s[side][0][k2l][n4]);
        blreg = *reinterpret_cast<const uint4*>(&g_W2s[side][1][k2l][n4]);
    }

    #pragma unroll 1
    for (int kt = 0; kt < 8; kt++) {
        __syncthreads();
        #pragma unroll
        for (int q = 0; q < 2; q++) {
            int idx = tid + q * 256;
            int row = idx >> 2, k2q = (idx & 3) * 4;
            *reinterpret_cast<uint4*>(&Ah[row][k2q]) = ahreg[q];
            *reinterpret_cast<uint4*>(&Al[row][k2q]) = alreg[q];
        }
        {
            int k2l = tid >> 4, n4 = (tid & 15) * 4;
            *reinterpret_cast<uint4*>(&Bh[k2l][n4]) = bhreg;
            *reinterpret_cast<uint4*>(&Bl[k2l][n4]) = blreg;
        }
        __syncthreads();

        if (kt + 1 < 8) {
            int k2n = (kt + 1) * 16;
            #pragma unroll
            for (int q = 0; q < 2; q++) {
                int idx = tid + q * 256;
                int row = idx >> 2, k2q = (idx & 3) * 4;
                ahreg[q] = *reinterpret_cast<const uint4*>(&g_acth[side][row0 + row][k2n + k2q]);
                alreg[q] = *reinterpret_cast<const uint4*>(&g_actl[side][row0 + row][k2n + k2q]);
            }
            int k2l = tid >> 4, n4 = (tid & 15) * 4;
            bhreg = *reinterpret_cast<const uint4*>(&g_W2s[side][0][k2n + k2l][n4]);
            blreg = *reinterpret_cast<const uint4*>(&g_W2s[side][1][k2n + k2l][n4]);
        }

        #pragma unroll
        for (int k8x = 0; k8x < 16; k8x += 8) {
            uint32_t ah[2][4], al2[2][4], bh[4][2], bl[4][2];
            #pragma unroll
            for (int mt = 0; mt < 2; mt++) {
                int r = wr0 + mt * 16 + gid;
                ah[mt][0] = Ah[r][k8x + tig];     ah[mt][1] = Ah[r + 8][k8x + tig];
                ah[mt][2] = Ah[r][k8x + tig + 4]; ah[mt][3] = Ah[r + 8][k8x + tig + 4];
                al2[mt][0] = Al[r][k8x + tig];     al2[mt][1] = Al[r + 8][k8x + tig];
                al2[mt][2] = Al[r][k8x + tig + 4]; al2[mt][3] = Al[r + 8][k8x + tig + 4];
            }
            #pragma unroll
            for (int nt = 0; nt < 4; nt++) {
                int c = wc0 + nt * 8 + gid;
                bh[nt][0] = Bh[k8x + tig][c]; bh[nt][1] = Bh[k8x + tig + 4][c];
                bl[nt][0] = Bl[k8x + tig][c]; bl[nt][1] = Bl[k8x + tig + 4][c];
            }
            #pragma unroll
            for (int mt = 0; mt < 2; mt++)
                #pragma unroll
                for (int nt = 0; nt < 4; nt++) {
                    MMA_BF16(acc[mt][nt], ah[mt], bh[nt]);
                    MMA_BF16(acc[mt][nt], al2[mt], bh[nt]);
                    MMA_BF16(acc[mt][nt], ah[mt], bl[nt]);
                }
        }
    }

    #pragma unroll
    for (int mt = 0; mt < 2; mt++)
        #pragma unroll
        for (int nt = 0; nt < 4; nt++) {
            int r = row0 + wr0 + mt * 16 + gid;
            int c = wc0 + nt * 8 + tig * 2;
            float b0 = b2[c], b1b = b2[c + 1];
            float2 v0 = {acc[mt][nt][0] + b0, acc[mt][nt][1] + b1b};
            float2 v1 = {acc[mt][nt][2] + b0, acc[mt][nt][3] + b1b};
            *reinterpret_cast<float2*>(&g_m[side][r][c])     = v0;
            *reinterpret_cast<float2*>(&g_m[side][r + 8][c]) = v1;
        }
}

// ---------------------------------------------------------------------------
// VQ: Clifford collapse per row -> packed split Q.  Warp per row. (unchanged)
// ---------------------------------------------------------------------------
__global__ __launch_bounds__(256) void k_vq(const float* __restrict__ gw)
{
    __shared__ float s_gw[8];
    __shared__ float s_mp[8][64], s_mv[8][64], s_V[8][64], s_Q[8][64];

    const int tid = threadIdx.x;
    const int lane = tid & 31;
    const int w = tid >> 5;

    if (tid < 8) s_gw[tid] = gw[tid];
    __syncthreads();

    const int row = blockIdx.x * 8 + w;

    s_mp[w][lane]      = g_m[0][row][lane];
    s_mp[w][lane + 32] = g_m[0][row][lane + 32];
    s_mv[w][lane]      = g_m[1][row][lane];
    s_mv[w][lane + 32] = g_m[1][row][lane + 32];
    __syncwarp();

    const int MASKS_[8] = {0, 1, 2, 4, 3, 5, 6, 7};

    #pragma unroll
    for (int h = 0; h < 2; h++) {
        int f = lane + h * 32;
        int k = f >> 3, u = f & 7;
        float v = 0.0f;
        #pragma unroll
        for (int jm = 0; jm < 8; jm++) {
            int mj = MASKS_[jm];
            v += s_mv[w][k * 8 + jm] * csign(u, mj) * s_gw[cidx(u ^ mj)];
        }
        s_V[w][f] = v;
    }
    __syncwarp();

    #pragma unroll
    for (int h = 0; h < 2; h++) {
        int f = lane + h * 32;
        int k = f >> 3, jc = f & 7;
        int mjc = MASKS_[jc];
        float q = 0.0f;
        #pragma unroll
        for (int i = 0; i < 8; i++) {
            int mi = MASKS_[i];
            q += s_mp[w][k * 8 + i] * csign(mi, mjc) * s_V[w][k * 8 + (mi ^ mjc)];
        }
        s_Q[w][f] = q;
    }
    __syncwarp();

    uint32_t hp, lp;
    bf16_split_pack(s_Q[w][2 * lane], s_Q[w][2 * lane + 1], hp, lp);
    g_Qh[row][lane] = hp;
    g_Ql[row][lane] = lp;
}

// ---------------------------------------------------------------------------
// READ: out(B,95) = Q(B,64) @ T'(64,95)  (T pre-scaled 1/8), bf16 3x. (unchanged)
// ---------------------------------------------------------------------------
__global__ __launch_bounds__(256, 2) void k_read(float* __restrict__ out)
{
    __shared__ uint32_t Ah[128][20], Al[128][20], Bh[16][136], Bl[16][136];

    const int tid  = threadIdx.x;
    const int lane = tid & 31;
    const int wid  = tid >> 5;
    const int gid  = lane >> 2;
    const int tig  = lane & 3;
    const int wr0  = (wid & 3) * 32;
    const int wc0  = (wid >> 2) * 48;
    const int row0 = blockIdx.x * 128;

    float acc[2][6][4];
    #pragma unroll
    for (int mt = 0; mt < 2; mt++)
        #pragma unroll
        for (int nt = 0; nt < 6; nt++)
            #pragma unroll
            for (int e = 0; e < 4; e++) acc[mt][nt][e] = 0.0f;

    uint4 ahreg[2], alreg[2], bhreg[2], blreg[2];
    #pragma unroll
    for (int q = 0; q < 2; q++) {
        int idx = tid + q * 256;
        int row = idx >> 2, k2q = (idx & 3) * 4;
        ahreg[q] = *reinterpret_cast<const uint4*>(&g_Qh[row0 + row][k2q]);
        alreg[q] = *reinterpret_cast<const uint4*>(&g_Ql[row0 + row][k2q]);
        int k2l = idx >> 5, n4 = (idx & 31) * 4;
        bhreg[q] = *reinterpret_cast<const uint4*>(&g_Th[k2l][n4]);
        blreg[q] = *reinterpret_cast<const uint4*>(&g_Tl[k2l][n4]);
    }

    #pragma unroll 1
    for (int kt = 0; kt < 2; kt++) {
        __syncthreads();
        #pragma unroll
        for (int q = 0; q < 2; q++) {
            int idx = tid + q * 256;
            int row = idx >> 2, k2q = (idx & 3) * 4;
            *reinterpret_cast<uint4*>(&Ah[row][k2q]) = ahreg[q];
            *reinterpret_cast<uint4*>(&Al[row][k2q]) = alreg[q];
            int k2l = idx >> 5, n4 = (idx & 31) * 4;
            *reinterpret_cast<uint4*>(&Bh[k2l][n4]) = bhreg[q];
            *reinterpret_cast<uint4*>(&Bl[k2l][n4]) = blreg[q];
        }
        __syncthreads();

        if (kt == 0) {
            #pragma unroll
            for (int q = 0; q < 2; q++) {
                int idx = tid + q * 256;
                int row = idx >> 2, k2q = (idx & 3) * 4;
                ahreg[q] = *reinterpret_cast<const uint4*>(&g_Qh[row0 + row][16 + k2q]);
                alreg[q] = *reinterpret_cast<const uint4*>(&g_Ql[row0 + row][16 + k2q]);
                int k2l = idx >> 5, n4 = (idx & 31) * 4;
                bhreg[q] = *reinterpret_cast<const uint4*>(&g_Th[16 + k2l][n4]);
                blreg[q] = *reinterpret_cast<const uint4*>(&g_Tl[16 + k2l][n4]);
            }
        }

        #pragma unroll
        for (int k8x = 0; k8x < 16; k8x += 8) {
            uint32_t ah[2][4], al2[2][4], bh[6][2], bl[6][2];
            #pragma unroll
            for (int mt = 0; mt < 2; mt++) {
                int r = wr0 + mt * 16 + gid;
                ah[mt][0] = Ah[r][k8x + tig];     ah[mt][1] = Ah[r + 8][k8x + tig];
                ah[mt][2] = Ah[r][k8x + tig + 4]; ah[mt][3] = Ah[r + 8][k8x + tig + 4];
                al2[mt][0] = Al[r][k8x + tig];     al2[mt][1] = Al[r + 8][k8x + tig];
                al2[mt][2] = Al[r][k8x + tig + 4]; al2[mt][3] = Al[r + 8][k8x + tig + 4];
            }
            #pragma unroll
            for (int nt = 0; nt < 6; nt++) {
                int c = wc0 + nt * 8 + gid;
                bh[nt][0] = Bh[k8x + tig][c]; bh[nt][1] = Bh[k8x + tig + 4][c];
                bl[nt][0] = Bl[k8x + tig][c]; bl[nt][1] = Bl[k8x + tig + 4][c];
            }
            #pragma unroll
            for (int mt = 0; mt < 2; mt++)
                #pragma unroll
                for (int nt = 0; nt < 6; nt++) {
                    MMA_BF16(acc[mt][nt], ah[mt], bh[nt]);
                    MMA_BF16(acc[mt][nt], al2[mt], bh[nt]);
                    MMA_BF16(acc[mt][nt], ah[mt], bl[nt]);
                }
        }
    }

    #pragma unroll
    for (int mt = 0; mt < 2; mt++)
        #pragma unroll
        for (int nt = 0; nt < 6; nt++) {
            int r = row0 + wr0 + mt * 16 + gid;
            int c = wc0 + nt * 8 + tig * 2;
            if (c < Rr)     out[r * Rr + c]             = acc[mt][nt][0];
            if (c + 1 < Rr) out[r * Rr + c + 1]         = acc[mt][nt][1];
            if (c < Rr)     out[(r + 8) * Rr + c]       = acc[mt][nt][2];
            if (c + 1 < Rr) out[(r + 8) * Rr + c + 1]   = acc[mt][nt][3];
        }
}

// ---------------------------------------------------------------------------
extern "C" void kernel_launch(void* const* d_in, const int* in_sizes, int n_in,
                              void* d_out, int out_size)
{
    const float* h_perp = (const float*)d_in[0];
    const float* h_vuln = (const float*)d_in[1];
    const float* Wp1    = (const float*)d_in[2];
    const float* bp1    = (const float*)d_in[3];
    const float* lgp    = (const float*)d_in[4];
    const float* lbp    = (const float*)d_in[5];
    const float* Wp2    = (const float*)d_in[6];
    const float* bp2    = (const float*)d_in[7];
    const float* Wv1    = (const float*)d_in[8];
    const float* bv1    = (const float*)d_in[9];
    const float* lgv    = (const float*)d_in[10];
    const float* lbv    = (const float*)d_in[11];
    const float* Wv2    = (const float*)d_in[12];
    const float* bv2    = (const float*)d_in[13];
    const float* T      = (const float*)d_in[14];
    const float* gw     = (const float*)d_in[15];
    float* out = (float*)d_out;

    k_prep<<<(N_W1 + N_W2 + N_T + 255) / 256, 256>>>(Wp1, Wv1, Wp2, Wv2, T);
    k_gemm1f<<<dim3(Bsz / 64, 2), 512>>>(h_perp, h_vuln,
        bp1, bv1, lgp, lgv, lbp, lbv);
    k_gemm2<<<dim3(Bsz / 128, 2), 256>>>(bp2, bv2);
    k_vq<<<Bsz / 8, 256>>>(gw);
    k_read<<<Bsz / 128, 256>>>(out);
}

// round 15
// speedup vs baseline: 1.1466x; 1.1466x over previous
#include <cuda_runtime.h>
#include <cuda_bf16.h>
#include <stdint.h>

#define Bsz 16384
#define Dd 512
#define Hh 256
#define Rr 95

// ------------------------------- scratch -----------------------------------
__device__ uint32_t g_acth[2][Bsz][Hh / 2];   // post-GELU acts, bf16x2 hi
__device__ uint32_t g_actl[2][Bsz][Hh / 2];   // post-GELU acts, bf16x2 lo
__device__ float    g_m[2][Bsz][64];          // mp / mv multivectors
__device__ uint32_t g_W1s[2][2][Dd / 2][Hh];  // [side][hi/lo][k2][n]
__device__ uint32_t g_W2s[2][2][Hh / 2][64];
__device__ uint32_t g_Qh[Bsz][32];            // Q collapsed, bf16x2 hi (k2)
__device__ uint32_t g_Ql[Bsz][32];
__device__ uint32_t g_Th[32][128];            // T*0.125 pre-split [k2][n(pad 128)]
__device__ uint32_t g_Tl[32][128];

// ------------------------------- helpers -----------------------------------
__device__ __forceinline__ float gelu_exact(float x) {
    return 0.5f * x * (1.0f + erff(x * 0.70710678118654752440f));
}
__device__ __forceinline__ float csign(int a, int b) {
    int sw = __popc((a >> 1) & b) + __popc((a >> 2) & b);
    return (sw & 1) ? -1.0f : 1.0f;
}
__device__ __forceinline__ int cidx(int m) { return m + (m == 3) - (m == 4); }

__device__ __forceinline__ void bf16_split_pack(float x0, float x1,
                                                uint32_t& hp, uint32_t& lp) {
    __nv_bfloat16 h0 = __float2bfloat16(x0), h1 = __float2bfloat16(x1);
    float r0 = x0 - __bfloat162float(h0);
    float r1 = x1 - __bfloat162float(h1);
    __nv_bfloat16 l0 = __float2bfloat16(r0), l1 = __float2bfloat16(r1);
    hp = ((uint32_t)__bfloat16_as_ushort(h1) << 16) | (uint32_t)__bfloat16_as_ushort(h0);
    lp = ((uint32_t)__bfloat16_as_ushort(l1) << 16) | (uint32_t)__bfloat16_as_ushort(l0);
}

#define MMA_BF16(d, a, b) \
    asm volatile("mma.sync.aligned.m16n8k16.row.col.f32.bf16.bf16.f32 " \
        "{%0,%1,%2,%3}, {%4,%5,%6,%7}, {%8,%9}, {%0,%1,%2,%3};" \
        : "+f"(d[0]), "+f"(d[1]), "+f"(d[2]), "+f"(d[3]) \
        : "r"(a[0]), "r"(a[1]), "r"(a[2]), "r"(a[3]), "r"(b[0]), "r"(b[1]))

__device__ __forceinline__ void cp16(uint32_t saddr, const void* g) {
    asm volatile("cp.async.cg.shared.global [%0], [%1], 16;" :: "r"(saddr), "l"(g));
}
#define CP_COMMIT() asm volatile("cp.async.commit_group;" ::: "memory")
#define CP_WAIT0()  asm volatile("cp.async.wait_group 0;"  ::: "memory")

// ---------------------------------------------------------------------------
// prep (merged): W1 split, W2 split, T split (pre-scaled 1/8)
// ---------------------------------------------------------------------------
#define N_W1 (2 * (Dd / 2) * Hh)          // 131072 (65536 = 2^16 per side)
#define N_W2 (2 * (Hh / 2) * 64)          // 16384  (8192  = 2^13 per side)
#define N_T  (32 * 128)                   // 4096
__global__ __launch_bounds__(256) void k_prep(
    const float* __restrict__ W1p, const float* __restrict__ W1v,
    const float* __restrict__ W2p, const float* __restrict__ W2v,
    const float* __restrict__ T)
{
    int idx = blockIdx.x * 256 + threadIdx.x;
    if (idx < N_W1) {
        int side = idx >> 16;
        int rem  = idx & 0xFFFF;
        int k2   = rem >> 8;
        int n    = rem & 255;
        const float* W = side ? W1v : W1p;
        float x0 = __ldg(&W[(2 * k2) * Hh + n]);
        float x1 = __ldg(&W[(2 * k2 + 1) * Hh + n]);
        uint32_t hp, lp;
        bf16_split_pack(x0, x1, hp, lp);
        g_W1s[side][0][k2][n] = hp;
        g_W1s[side][1][k2][n] = lp;
    } else if (idx < N_W1 + N_W2) {
        int j = idx - N_W1;
        int side = j >> 13;               // 8192 = 2^13 elements per side
        int rem  = j & 0x1FFF;
        int k2   = rem >> 6;              // 0..127
        int n    = rem & 63;
        const float* W = side ? W2v : W2p;
        float x0 = __ldg(&W[(2 * k2) * 64 + n]);
        float x1 = __ldg(&W[(2 * k2 + 1) * 64 + n]);
        uint32_t hp, lp;
        bf16_split_pack(x0, x1, hp, lp);
        g_W2s[side][0][k2][n] = hp;
        g_W2s[side][1][k2][n] = lp;
    } else if (idx < N_W1 + N_W2 + N_T) {
        int j = idx - N_W1 - N_W2;
        int k2 = j >> 7;
        int n  = j & 127;
        float x0 = 0.0f, x1 = 0.0f;
        if (n < Rr) {
            x0 = __ldg(&T[n * 64 + 2 * k2])     * 0.125f;
            x1 = __ldg(&T[n * 64 + 2 * k2 + 1]) * 0.125f;
        }
        uint32_t hp, lp;
        bf16_split_pack(x0, x1, hp, lp);
        g_Th[k2][n] = hp;
        g_Tl[k2][n] = lp;
    }
}

// ---------------------------------------------------------------------------
// GEMM1 fused + double-buffered (EXACT R11 config, 256 thr, 8 warps):
// Y = X@W1+b1 -> LN -> GELU. BM=64, BN=256, BK=16. Warp tile 64x32.
// Stage word layout: Ah [0,576) Al [576,1152) Bh [1152,3264) Bl [3264,5376)
// ---------------------------------------------------------------------------
#define STG_W 5376

__device__ __forceinline__ void stsA(uint32_t* __restrict__ dsm, int so,
                                     float4 a, int tid) {
    int row = tid >> 2, k2 = (tid & 3) * 2;
    uint32_t hp0, lp0, hp1, lp1;
    bf16_split_pack(a.x, a.y, hp0, lp0);
    bf16_split_pack(a.z, a.w, hp1, lp1);
    dsm[so + k2 * 72 + row]              = hp0;
    dsm[so + (k2 + 1) * 72 + row]        = hp1;
    dsm[so + 576 + k2 * 72 + row]        = lp0;
    dsm[so + 576 + (k2 + 1) * 72 + row]  = lp1;
}

__device__ __forceinline__ void cpB(uint32_t sdyn, int so, int side,
                                    int k2base, int tid) {
    #pragma unroll
    for (int q = 0; q < 2; q++) {
        int idx = tid + q * 256;
        int k2l = idx >> 6, n4 = (idx & 63) * 4;
        cp16(sdyn + (uint32_t)(so + 1152 + k2l * 264 + n4) * 4,
             &g_W1s[side][0][k2base + k2l][n4]);
        cp16(sdyn + (uint32_t)(so + 3264 + k2l * 264 + n4) * 4,
             &g_W1s[side][1][k2base + k2l][n4]);
    }
}

__global__ __launch_bounds__(256) void k_gemm1f(
    const float* __restrict__ Xp, const float* __restrict__ Xv,
    const float* __restrict__ b1p, const float* __restrict__ b1v,
    const float* __restrict__ lgp, const float* __restrict__ lgv,
    const float* __restrict__ lbp, const float* __restrict__ lbv)
{
    __shared__ __align__(16) uint32_t dsm[2 * STG_W];
    __shared__ float2 s_part[8][64];
    __shared__ float2 s_ln[64];

    const int side = blockIdx.y;
    const float* __restrict__ X  = side ? Xv : Xp;
    const float* __restrict__ b1 = side ? b1v : b1p;
    const float* __restrict__ lg = side ? lgv : lgp;
    const float* __restrict__ lb = side ? lbv : lbp;

    const int tid  = threadIdx.x;
    const int lane = tid & 31;
    const int wid  = tid >> 5;
    const int gid  = lane >> 2;
    const int tig  = lane & 3;
    const int wc0  = wid * 32;
    const int row0 = blockIdx.x * 64;
    const uint32_t sdyn = (uint32_t)__cvta_generic_to_shared(dsm);

    float acc[4][4][4];
    #pragma unroll
    for (int mt = 0; mt < 4; mt++)
        #pragma unroll
        for (int nt = 0; nt < 4; nt++)
            #pragma unroll
            for (int e = 0; e < 4; e++) acc[mt][nt][e] = 0.0f;

    const int arow = row0 + (tid >> 2);
    const int acol = (tid & 3) * 4;

    float4 areg;
    areg = *reinterpret_cast<const float4*>(&X[arow * Dd + acol]);
    stsA(dsm, 0, areg, tid);
    cpB(sdyn, 0, side, 0, tid);
    CP_COMMIT();
    areg = *reinterpret_cast<const float4*>(&X[arow * Dd + 16 + acol]);
    CP_WAIT0();
    __syncthreads();

    #pragma unroll 1
    for (int kt = 0; kt < 32; kt++) {
        const int cur = (kt & 1) * STG_W;
        const int nxt = ((kt & 1) ^ 1) * STG_W;

        if (kt < 31) {
            stsA(dsm, nxt, areg, tid);
            cpB(sdyn, nxt, side, (kt + 1) * 8, tid);
            CP_COMMIT();
            if (kt < 30) {
                int kn = (kt + 2) * 16;
                areg = *reinterpret_cast<const float4*>(&X[arow * Dd + kn + acol]);
            }
        }

        {
            uint32_t ah[4][4], al[4][4], bh[4][2], bl[4][2];
            #pragma unroll
            for (int mt = 0; mt < 4; mt++) {
                int r = mt * 16 + gid;
                ah[mt][0] = dsm[cur + tig * 72 + r];
                ah[mt][1] = dsm[cur + tig * 72 + r + 8];
                ah[mt][2] = dsm[cur + (tig + 4) * 72 + r];
                ah[mt][3] = dsm[cur + (tig + 4) * 72 + r + 8];
                al[mt][0] = dsm[cur + 576 + tig * 72 + r];
                al[mt][1] = dsm[cur + 576 + tig * 72 + r + 8];
                al[mt][2] = dsm[cur + 576 + (tig + 4) * 72 + r];
                al[mt][3] = dsm[cur + 576 + (tig + 4) * 72 + r + 8];
            }
            #pragma unroll
            for (int nt = 0; nt < 4; nt++) {
                int c = wc0 + nt * 8 + gid;
                bh[nt][0] = dsm[cur + 1152 + tig * 264 + c];
                bh[nt][1] = dsm[cur + 1152 + (tig + 4) * 264 + c];
                bl[nt][0] = dsm[cur + 3264 + tig * 264 + c];
                bl[nt][1] = dsm[cur + 3264 + (tig + 4) * 264 + c];
            }
            #pragma unroll
            for (int mt = 0; mt < 4; mt++)
                #pragma unroll
                for (int nt = 0; nt < 4; nt++) {
                    MMA_BF16(acc[mt][nt], ah[mt], bh[nt]);
                    MMA_BF16(acc[mt][nt], al[mt], bh[nt]);
                    MMA_BF16(acc[mt][nt], ah[mt], bl[nt]);
                }
        }

        if (kt < 31) {
            CP_WAIT0();
            __syncthreads();
        }
    }

    // ------------- fused epilogue: bias + LayerNorm + GELU + split ----------
    float bcol[8], lgc[8], lbc[8];
    #pragma unroll
    for (int nt = 0; nt < 4; nt++) {
        int c = wc0 + nt * 8 + tig * 2;
        bcol[nt * 2] = __ldg(&b1[c]); bcol[nt * 2 + 1] = __ldg(&b1[c + 1]);
        lgc[nt * 2]  = __ldg(&lg[c]); lgc[nt * 2 + 1]  = __ldg(&lg[c + 1]);
        lbc[nt * 2]  = __ldg(&lb[c]); lbc[nt * 2 + 1]  = __ldg(&lb[c + 1]);
    }

    float s[8], s2[8];
    #pragma unroll
    for (int q = 0; q < 8; q++) { s[q] = 0.0f; s2[q] = 0.0f; }
    #pragma unroll
    for (int mt = 0; mt < 4; mt++)
        #pragma unroll
        for (int nt = 0; nt < 4; nt++)
            #pragma unroll
            for (int e = 0; e < 4; e++) {
                float v = acc[mt][nt][e] + bcol[nt * 2 + (e & 1)];
                acc[mt][nt][e] = v;
                int slot = mt * 2 + (e >> 1);
                s[slot] += v; s2[slot] += v * v;
            }
    #pragma unroll
    for (int q = 0; q < 8; q++) {
        s[q]  += __shfl_xor_sync(0xffffffffu, s[q],  1);
        s[q]  += __shfl_xor_sync(0xffffffffu, s[q],  2);
        s2[q] += __shfl_xor_sync(0xffffffffu, s2[q], 1);
        s2[q] += __shfl_xor_sync(0xffffffffu, s2[q], 2);
    }
    __syncthreads();
    if (tig == 0) {
        #pragma unroll
        for (int mt = 0; mt < 4; mt++) {
            s_part[wid][mt * 16 + gid]     = make_float2(s[mt * 2],     s2[mt * 2]);
            s_part[wid][mt * 16 + 8 + gid] = make_float2(s[mt * 2 + 1], s2[mt * 2 + 1]);
        }
    }
    __syncthreads();
    if (tid < 64) {
        float ts = 0.0f, ts2 = 0.0f;
        #pragma unroll
        for (int w = 0; w < 8; w++) {
            float2 p = s_part[w][tid];
            ts += p.x; ts2 += p.y;
        }
        float mu   = ts * (1.0f / 256.0f);
        float var  = ts2 * (1.0f / 256.0f) - mu * mu;
        s_ln[tid] = make_float2(mu, rsqrtf(var + 1e-5f));
    }
    __syncthreads();

    #pragma unroll
    for (int mt = 0; mt < 4; mt++)
        #pragma unroll
        for (int h = 0; h < 2; h++) {
            int rl = mt * 16 + h * 8 + gid;
            float2 ln = s_ln[rl];
            int row = row0 + rl;
            #pragma unroll
            for (int nt = 0; nt < 4; nt++) {
                float v0 = acc[mt][nt][h * 2];
                float v1 = acc[mt][nt][h * 2 + 1];
                float y0 = gelu_exact((v0 - ln.x) * ln.y * lgc[nt * 2]     + lbc[nt * 2]);
                float y1 = gelu_exact((v1 - ln.x) * ln.y * lgc[nt * 2 + 1] + lbc[nt * 2 + 1]);
                uint32_t hp, lp;
                bf16_split_pack(y0, y1, hp, lp);
                int k2 = (wc0 >> 1) + nt * 4 + tig;
                g_acth[side][row][k2] = hp;
                g_actl[side][row][k2] = lp;
            }
        }
}

// ---------------------------------------------------------------------------
// GEMM2 double-buffered + cp.async: M(B,64) = act(B,256)@W2 + b2 -> g_m.
// BM=128, BN=64, BK=16 (8 k2). 8 warps (4m x 2n), warp tile 32x32.
// Stage words: Ah [0,1536) Al [1536,3072) Bh [3072,3648) Bl [3648,4224)
// A stride 12 ([row][k2]), B stride 72 ([k2][n]). 2 stages = 33792 B.
// ---------------------------------------------------------------------------
#define G2_STG 4224

__device__ __forceinline__ void g2_cp(uint32_t sdyn, int so, int side,
                                      int row0, int k2base, int tid) {
    // A: 2 cp16/thread (hi+lo): row = tid>>1 (0..127), quad = tid&1 (0..1)
    {
        int row = tid >> 1, quad = tid & 1;
        cp16(sdyn + (uint32_t)(so + row * 12 + quad * 4) * 4,
             &g_acth[side][row0 + row][k2base + quad * 4]);
        cp16(sdyn + (uint32_t)(so + 1536 + row * 12 + quad * 4) * 4,
             &g_actl[side][row0 + row][k2base + quad * 4]);
    }
    // B: 1 cp16/thread: k2l = tid>>5 (0..7), r = tid&31; hl = r>>4; n4 = r&15
    {
        int k2l = tid >> 5, r = tid & 31;
        int hl = r >> 4, n4 = r & 15;
        cp16(sdyn + (uint32_t)(so + 3072 + hl * 576 + k2l * 72 + n4 * 4) * 4,
             &g_W2s[side][hl][k2base + k2l][n4 * 4]);
    }
}

__global__ __launch_bounds__(256, 2) void k_gemm2(
    const float* __restrict__ b2p, const float* __restrict__ b2v)
{
    __shared__ __align__(16) uint32_t dsm[2 * G2_STG];

    const int side = blockIdx.y;
    const float* __restrict__ b2 = side ? b2v : b2p;

    const int tid  = threadIdx.x;
    const int lane = tid & 31;
    const int wid  = tid >> 5;
    const int gid  = lane >> 2;
    const int tig  = lane & 3;
    const int wr0  = (wid & 3) * 32;
    const int wc0  = (wid >> 2) * 32;
    const int row0 = blockIdx.x * 128;
    const uint32_t sdyn = (uint32_t)__cvta_generic_to_shared(dsm);

    float acc[2][4][4];
    #pragma unroll
    for (int mt = 0; mt < 2; mt++)
        #pragma unroll
        for (int nt = 0; nt < 4; nt++)
            #pragma unroll
            for (int e = 0; e < 4; e++) acc[mt][nt][e] = 0.0f;

    // prologue: stage 0
    g2_cp(sdyn, 0, side, row0, 0, tid);
    CP_COMMIT();
    CP_WAIT0();
    __syncthreads();

    #pragma unroll 1
    for (int kt = 0; kt < 16; kt++) {
        const int cur = (kt & 1) * G2_STG;
        const int nxt = ((kt & 1) ^ 1) * G2_STG;

        if (kt < 15) {
            g2_cp(sdyn, nxt, side, row0, (kt + 1) * 8, tid);
            CP_COMMIT();
        }

        {
            uint32_t ah[2][4], al2[2][4], bh[4][2], bl[4][2];
            #pragma unroll
            for (int mt = 0; mt < 2; mt++) {
                int r = wr0 + mt * 16 + gid;
                ah[mt][0] = dsm[cur + r * 12 + tig];
                ah[mt][1] = dsm[cur + (r + 8) * 12 + tig];
                ah[mt][2] = dsm[cur + r * 12 + tig + 4];
                ah[mt][3] = dsm[cur + (r + 8) * 12 + tig + 4];
                al2[mt][0] = dsm[cur + 1536 + r * 12 + tig];
                al2[mt][1] = dsm[cur + 1536 + (r + 8) * 12 + tig];
                al2[mt][2] = dsm[cur + 1536 + r * 12 + tig + 4];
                al2[mt][3] = dsm[cur + 1536 + (r + 8) * 12 + tig + 4];
            }
            #pragma unroll
            for (int nt = 0; nt < 4; nt++) {
                int c = wc0 + nt * 8 + gid;
                bh[nt][0] = dsm[cur + 3072 + tig * 72 + c];
                bh[nt][1] = dsm[cur + 3072 + (tig + 4) * 72 + c];
                bl[nt][0] = dsm[cur + 3648 + tig * 72 + c];
                bl[nt][1] = dsm[cur + 3648 + (tig + 4) * 72 + c];
            }
            #pragma unroll
            for (int mt = 0; mt < 2; mt++)
                #pragma unroll
                for (int nt = 0; nt < 4; nt++) {
                    MMA_BF16(acc[mt][nt], ah[mt], bh[nt]);
                    MMA_BF16(acc[mt][nt], al2[mt], bh[nt]);
                    MMA_BF16(acc[mt][nt], ah[mt], bl[nt]);
                }
        }

        if (kt < 15) {
            CP_WAIT0();
            __syncthreads();
        }
    }

    #pragma unroll
    for (int mt = 0; mt < 2; mt++)
        #pragma unroll
        for (int nt = 0; nt < 4; nt++) {
            int r = row0 + wr0 + mt * 16 + gid;
            int c = wc0 + nt * 8 + tig * 2;
            float b0 = b2[c], b1b = b2[c + 1];
            float2 v0 = {acc[mt][nt][0] + b0, acc[mt][nt][1] + b1b};
            float2 v1 = {acc[mt][nt][2] + b0, acc[mt][nt][3] + b1b};
            *reinterpret_cast<float2*>(&g_m[side][r][c])     = v0;
            *reinterpret_cast<float2*>(&g_m[side][r + 8][c]) = v1;
        }
}

// ---------------------------------------------------------------------------
// VQ: Clifford collapse per row -> packed split Q.  Warp per row.
// V-stage coefficients pre-tabulated: cV[u][jm] = csign(u,mj)*gw[cidx(u^mj)],
// loaded once per thread into registers (u = lane&7 is h-invariant).
// ---------------------------------------------------------------------------
__global__ __launch_bounds__(256) void k_vq(const float* __restrict__ gw)
{
    __shared__ float s_cV[64];
    __shared__ float s_mp[8][64], s_mv[8][64], s_V[8][64], s_Q[8][64];

    const int tid = threadIdx.x;
    const int lane = tid & 31;
    const int w = tid >> 5;

    const int MASKS_[8] = {0, 1, 2, 4, 3, 5, 6, 7};

    if (tid < 64) {
        int u = tid >> 3, jm = tid & 7;
        int mj = MASKS_[jm];
        s_cV[tid] = csign(u, mj) * __ldg(&gw[cidx(u ^ mj)]);
    }
    __syncthreads();

    const int row = blockIdx.x * 8 + w;

    s_mp[w][lane]      = g_m[0][row][lane];
    s_mp[w][lane + 32] = g_m[0][row][lane + 32];
    s_mv[w][lane]      = g_m[1][row][lane];
    s_mv[w][lane + 32] = g_m[1][row][lane + 32];

    // per-thread V coefficients (u fixed = lane&7)
    const int u = lane & 7;
    float rc[8];
    #pragma unroll
    for (int jm = 0; jm < 8; jm++) rc[jm] = s_cV[u * 8 + jm];
    __syncwarp();

    #pragma unroll
    for (int h = 0; h < 2; h++) {
        int f = lane + h * 32;
        int k = f >> 3;
        float v = 0.0f;
        #pragma unroll
        for (int jm = 0; jm < 8; jm++)
            v = fmaf(s_mv[w][k * 8 + jm], rc[jm], v);
        s_V[w][f] = v;
    }
    __syncwarp();

    #pragma unroll
    for (int h = 0; h < 2; h++) {
        int f = lane + h * 32;
        int k = f >> 3, jc = f & 7;
        int mjc = MASKS_[jc];
        float q = 0.0f;
        #pragma unroll
        for (int i = 0; i < 8; i++) {
            int mi = MASKS_[i];
            q += s_mp[w][k * 8 + i] * csign(mi, mjc) * s_V[w][k * 8 + (mi ^ mjc)];
        }
        s_Q[w][f] = q;
    }
    __syncwarp();

    uint32_t hp, lp;
    bf16_split_pack(s_Q[w][2 * lane], s_Q[w][2 * lane + 1], hp, lp);
    g_Qh[row][lane] = hp;
    g_Ql[row][lane] = lp;
}

// ---------------------------------------------------------------------------
// READ: out(B,95) = Q(B,64) @ T'(64,95)  (T pre-scaled 1/8), bf16 3x. (unchanged)
// ---------------------------------------------------------------------------
__global__ __launch_bounds__(256, 2) void k_read(float* __restrict__ out)
{
    __shared__ uint32_t Ah[128][20], Al[128][20], Bh[16][136], Bl[16][136];

    const int tid  = threadIdx.x;
    const int lane = tid & 31;
    const int wid  = tid >> 5;
    const int gid  = lane >> 2;
    const int tig  = lane & 3;
    const int wr0  = (wid & 3) * 32;
    const int wc0  = (wid >> 2) * 48;
    const int row0 = blockIdx.x * 128;

    float acc[2][6][4];
    #pragma unroll
    for (int mt = 0; mt < 2; mt++)
        #pragma unroll
        for (int nt = 0; nt < 6; nt++)
            #pragma unroll
            for (int e = 0; e < 4; e++) acc[mt][nt][e] = 0.0f;

    uint4 ahreg[2], alreg[2], bhreg[2], blreg[2];
    #pragma unroll
    for (int q = 0; q < 2; q++) {
        int idx = tid + q * 256;
        int row = idx >> 2, k2q = (idx & 3) * 4;
        ahreg[q] = *reinterpret_cast<const uint4*>(&g_Qh[row0 + row][k2q]);
        alreg[q] = *reinterpret_cast<const uint4*>(&g_Ql[row0 + row][k2q]);
        int k2l = idx >> 5, n4 = (idx & 31) * 4;
        bhreg[q] = *reinterpret_cast<const uint4*>(&g_Th[k2l][n4]);
        blreg[q] = *reinterpret_cast<const uint4*>(&g_Tl[k2l][n4]);
    }

    #pragma unroll 1
    for (int kt = 0; kt < 2; kt++) {
        __syncthreads();
        #pragma unroll
        for (int q = 0; q < 2; q++) {
            int idx = tid + q * 256;
            int row = idx >> 2, k2q = (idx & 3) * 4;
            *reinterpret_cast<uint4*>(&Ah[row][k2q]) = ahreg[q];
            *reinterpret_cast<uint4*>(&Al[row][k2q]) = alreg[q];
            int k2l = idx >> 5, n4 = (idx & 31) * 4;
            *reinterpret_cast<uint4*>(&Bh[k2l][n4]) = bhreg[q];
            *reinterpret_cast<uint4*>(&Bl[k2l][n4]) = blreg[q];
        }
        __syncthreads();

        if (kt == 0) {
            #pragma unroll
            for (int q = 0; q < 2; q++) {
                int idx = tid + q * 256;
                int row = idx >> 2, k2q = (idx & 3) * 4;
                ahreg[q] = *reinterpret_cast<const uint4*>(&g_Qh[row0 + row][16 + k2q]);
                alreg[q] = *reinterpret_cast<const uint4*>(&g_Ql[row0 + row][16 + k2q]);
                int k2l = idx >> 5, n4 = (idx & 31) * 4;
                bhreg[q] = *reinterpret_cast<const uint4*>(&g_Th[16 + k2l][n4]);
                blreg[q] = *reinterpret_cast<const uint4*>(&g_Tl[16 + k2l][n4]);
            }
        }

        #pragma unroll
        for (int k8x = 0; k8x < 16; k8x += 8) {
            uint32_t ah[2][4], al2[2][4], bh[6][2], bl[6][2];
            #pragma unroll
            for (int mt = 0; mt < 2; mt++) {
                int r = wr0 + mt * 16 + gid;
                ah[mt][0] = Ah[r][k8x + tig];     ah[mt][1] = Ah[r + 8][k8x + tig];
                ah[mt][2] = Ah[r][k8x + tig + 4]; ah[mt][3] = Ah[r + 8][k8x + tig + 4];
                al2[mt][0] = Al[r][k8x + tig];     al2[mt][1] = Al[r + 8][k8x + tig];
                al2[mt][2] = Al[r][k8x + tig + 4]; al2[mt][3] = Al[r + 8][k8x + tig + 4];
            }
            #pragma unroll
            for (int nt = 0; nt < 6; nt++) {
                int c = wc0 + nt * 8 + gid;
                bh[nt][0] = Bh[k8x + tig][c]; bh[nt][1] = Bh[k8x + tig + 4][c];
                bl[nt][0] = Bl[k8x + tig][c]; bl[nt][1] = Bl[k8x + tig + 4][c];
            }
            #pragma unroll
            for (int mt = 0; mt < 2; mt++)
                #pragma unroll
                for (int nt = 0; nt < 6; nt++) {
                    MMA_BF16(acc[mt][nt], ah[mt], bh[nt]);
                    MMA_BF16(acc[mt][nt], al2[mt], bh[nt]);
                    MMA_BF16(acc[mt][nt], ah[mt], bl[nt]);
                }
        }
    }

    #pragma unroll
    for (int mt = 0; mt < 2; mt++)
        #pragma unroll
        for (int nt = 0; nt < 6; nt++) {
            int r = row0 + wr0 + mt * 16 + gid;
            int c = wc0 + nt * 8 + tig * 2;
            if (c < Rr)     out[r * Rr + c]             = acc[mt][nt][0];
            if (c + 1 < Rr) out[r * Rr + c + 1]         = acc[mt][nt][1];
            if (c < Rr)     out[(r + 8) * Rr + c]       = acc[mt][nt][2];
            if (c + 1 < Rr) out[(r + 8) * Rr + c + 1]   = acc[mt][nt][3];
        }
}

// ---------------------------------------------------------------------------
extern "C" void kernel_launch(void* const* d_in, const int* in_sizes, int n_in,
                              void* d_out, int out_size)
{
    const float* h_perp = (const float*)d_in[0];
    const float* h_vuln = (const float*)d_in[1];
    const float* Wp1    = (const float*)d_in[2];
    const float* bp1    = (const float*)d_in[3];
    const float* lgp    = (const float*)d_in[4];
    const float* lbp    = (const float*)d_in[5];
    const float* Wp2    = (const float*)d_in[6];
    const float* bp2    = (const float*)d_in[7];
    const float* Wv1    = (const float*)d_in[8];
    const float* bv1    = (const float*)d_in[9];
    const float* lgv    = (const float*)d_in[10];
    const float* lbv    = (const float*)d_in[11];
    const float* Wv2    = (const float*)d_in[12];
    const float* bv2    = (const float*)d_in[13];
    const float* T      = (const float*)d_in[14];
    const float* gw     = (const float*)d_in[15];
    float* out = (float*)d_out;

    k_prep<<<(N_W1 + N_W2 + N_T + 255) / 256, 256>>>(Wp1, Wv1, Wp2, Wv2, T);
    k_gemm1f<<<dim3(Bsz / 64, 2), 256>>>(h_perp, h_vuln,
        bp1, bv1, lgp, lgv, lbp, lbv);
    k_gemm2<<<dim3(Bsz / 128, 2), 256>>>(bp2, bv2);
    k_vq<<<Bsz / 8, 256>>>(gw);
    k_read<<<Bsz / 128, 256>>>(out);
}

// round 17
// speedup vs baseline: 1.1522x; 1.0049x over previous
#include <cuda_runtime.h>
#include <cuda_bf16.h>
#include <stdint.h>

#define Bsz 16384
#define Dd 512
#define Hh 256
#define Rr 95

// ------------------------------- scratch -----------------------------------
__device__ uint32_t g_acth[2][Bsz][Hh / 2];   // post-GELU acts, bf16x2 hi
__device__ uint32_t g_actl[2][Bsz][Hh / 2];   // post-GELU acts, bf16x2 lo
__device__ float    g_m[2][Bsz][64];          // side0: mp ; side1: V (pre-collapsed)
__device__ uint32_t g_W1s[2][2][Dd / 2][Hh];  // [side][hi/lo][k2][n]
__device__ uint32_t g_W2s[2][2][Hh / 2][64];  // side1 cols pre-transformed by C
__device__ float    g_b2t[64];                // b2v @ C (side1 bias)
__device__ uint32_t g_Qh[Bsz][32];            // Q collapsed, bf16x2 hi (k2)
__device__ uint32_t g_Ql[Bsz][32];
__device__ uint32_t g_Th[32][128];            // T*0.125 pre-split [k2][n(pad 128)]
__device__ uint32_t g_Tl[32][128];

// ------------------------------- helpers -----------------------------------
__device__ __forceinline__ float gelu_exact(float x) {
    return 0.5f * x * (1.0f + erff(x * 0.70710678118654752440f));
}
__device__ __forceinline__ float csign(int a, int b) {
    int sw = __popc((a >> 1) & b) + __popc((a >> 2) & b);
    return (sw & 1) ? -1.0f : 1.0f;
}
__device__ __forceinline__ int cidx(int m) { return m + (m == 3) - (m == 4); }

__device__ __forceinline__ void bf16_split_pack(float x0, float x1,
                                                uint32_t& hp, uint32_t& lp) {
    __nv_bfloat16 h0 = __float2bfloat16(x0), h1 = __float2bfloat16(x1);
    float r0 = x0 - __bfloat162float(h0);
    float r1 = x1 - __bfloat162float(h1);
    __nv_bfloat16 l0 = __float2bfloat16(r0), l1 = __float2bfloat16(r1);
    hp = ((uint32_t)__bfloat16_as_ushort(h1) << 16) | (uint32_t)__bfloat16_as_ushort(h0);
    lp = ((uint32_t)__bfloat16_as_ushort(l1) << 16) | (uint32_t)__bfloat16_as_ushort(l0);
}

#define MMA_BF16(d, a, b) \
    asm volatile("mma.sync.aligned.m16n8k16.row.col.f32.bf16.bf16.f32 " \
        "{%0,%1,%2,%3}, {%4,%5,%6,%7}, {%8,%9}, {%0,%1,%2,%3};" \
        : "+f"(d[0]), "+f"(d[1]), "+f"(d[2]), "+f"(d[3]) \
        : "r"(a[0]), "r"(a[1]), "r"(a[2]), "r"(a[3]), "r"(b[0]), "r"(b[1]))

__device__ __forceinline__ void cp16(uint32_t saddr, const void* g) {
    asm volatile("cp.async.cg.shared.global [%0], [%1], 16;" :: "r"(saddr), "l"(g));
}
#define CP_COMMIT() asm volatile("cp.async.commit_group;" ::: "memory")
#define CP_WAIT0()  asm volatile("cp.async.wait_group 0;"  ::: "memory")
#define CP_WAIT1()  asm volatile("cp.async.wait_group 1;"  ::: "memory")

// ---------------------------------------------------------------------------
// prep (merged): W1 split, W2 split (side1 cols xformed by C), T split, b2t
// ---------------------------------------------------------------------------
#define N_W1 (2 * (Dd / 2) * Hh)          // 131072 (2^16 per side)
#define N_W2 (2 * (Hh / 2) * 64)          // 16384  (2^13 per side)
#define N_T  (32 * 128)                   // 4096
#define N_ALL (N_W1 + N_W2 + N_T + 64)
__global__ __launch_bounds__(256) void k_prep(
    const float* __restrict__ W1p, const float* __restrict__ W1v,
    const float* __restrict__ W2p, const float* __restrict__ W2v,
    const float* __restrict__ T,   const float* __restrict__ gw,
    const float* __restrict__ b2v)
{
    const int MASKS_[8] = {0, 1, 2, 4, 3, 5, 6, 7};
    int idx = blockIdx.x * 256 + threadIdx.x;
    if (idx < N_W1) {
        int side = idx >> 16;
        int rem  = idx & 0xFFFF;
        int k2   = rem >> 8;
        int n    = rem & 255;
        const float* W = side ? W1v : W1p;
        float x0 = __ldg(&W[(2 * k2) * Hh + n]);
        float x1 = __ldg(&W[(2 * k2 + 1) * Hh + n]);
        uint32_t hp, lp;
        bf16_split_pack(x0, x1, hp, lp);
        g_W1s[side][0][k2][n] = hp;
        g_W1s[side][1][k2][n] = lp;
    } else if (idx < N_W1 + N_W2) {
        int j = idx - N_W1;
        int side = j >> 13;
        int rem  = j & 0x1FFF;
        int k2   = rem >> 6;
        int n    = rem & 63;
        float x0, x1;
        if (side == 0) {
            x0 = __ldg(&W2p[(2 * k2) * 64 + n]);
            x1 = __ldg(&W2p[(2 * k2 + 1) * 64 + n]);
        } else {
            // V-fold: col n=k*8+u gets sum_jm W2v[.., k*8+jm] * c(u,jm)
            int u = n & 7, nb = n & ~7;
            x0 = 0.0f; x1 = 0.0f;
            #pragma unroll
            for (int jm = 0; jm < 8; jm++) {
                int mj = MASKS_[jm];
                float c = csign(u, mj) * __ldg(&gw[cidx(u ^ mj)]);
                x0 += __ldg(&W2v[(2 * k2) * 64 + nb + jm]) * c;
                x1 += __ldg(&W2v[(2 * k2 + 1) * 64 + nb + jm]) * c;
            }
        }
        uint32_t hp, lp;
        bf16_split_pack(x0, x1, hp, lp);
        g_W2s[side][0][k2][n] = hp;
        g_W2s[side][1][k2][n] = lp;
    } else if (idx < N_W1 + N_W2 + N_T) {
        int j = idx - N_W1 - N_W2;
        int k2 = j >> 7;
        int n  = j & 127;
        float x0 = 0.0f, x1 = 0.0f;
        if (n < Rr) {
            x0 = __ldg(&T[n * 64 + 2 * k2])     * 0.125f;
            x1 = __ldg(&T[n * 64 + 2 * k2 + 1]) * 0.125f;
        }
        uint32_t hp, lp;
        bf16_split_pack(x0, x1, hp, lp);
        g_Th[k2][n] = hp;
        g_Tl[k2][n] = lp;
    } else if (idx < N_ALL) {
        int n = idx - (N_W1 + N_W2 + N_T);   // 0..63
        int u = n & 7, nb = n & ~7;
        float v = 0.0f;
        #pragma unroll
        for (int jm = 0; jm < 8; jm++) {
            int mj = MASKS_[jm];
            v += __ldg(&b2v[nb + jm]) * csign(u, mj) * __ldg(&gw[cidx(u ^ mj)]);
        }
        g_b2t[n] = v;
    }
}

// ---------------------------------------------------------------------------
// GEMM1 fused + 3-stage cp.async pipeline (dynamic smem 64.5KB):
// Y = X@W1+b1 -> LN -> GELU. BM=64, BN=256, BK=16. 8 warps, warp tile 64x32.
// Stage word layout: Ah [0,576) Al [576,1152) Bh [1152,3264) Bl [3264,5376)
// ---------------------------------------------------------------------------
#define STG_W 5376
#define DSMEM_G1 (3 * STG_W * 4)

__device__ __forceinline__ void stsA(uint32_t* __restrict__ dsm, int so,
                                     float4 a, int tid) {
    int row = tid >> 2, k2 = (tid & 3) * 2;
    uint32_t hp0, lp0, hp1, lp1;
    bf16_split_pack(a.x, a.y, hp0, lp0);
    bf16_split_pack(a.z, a.w, hp1, lp1);
    dsm[so + k2 * 72 + row]              = hp0;
    dsm[so + (k2 + 1) * 72 + row]        = hp1;
    dsm[so + 576 + k2 * 72 + row]        = lp0;
    dsm[so + 576 + (k2 + 1) * 72 + row]  = lp1;
}

__device__ __forceinline__ void cpB(uint32_t sdyn, int so, int side,
                                    int k2base, int tid) {
    #pragma unroll
    for (int q = 0; q < 2; q++) {
        int idx = tid + q * 256;
        int k2l = idx >> 6, n4 = (idx & 63) * 4;
        cp16(sdyn + (uint32_t)(so + 1152 + k2l * 264 + n4) * 4,
             &g_W1s[side][0][k2base + k2l][n4]);
        cp16(sdyn + (uint32_t)(so + 3264 + k2l * 264 + n4) * 4,
             &g_W1s[side][1][k2base + k2l][n4]);
    }
}

__global__ __launch_bounds__(256) void k_gemm1f(
    const float* __restrict__ Xp, const float* __restrict__ Xv,
    const float* __restrict__ b1p, const float* __restrict__ b1v,
    const float* __restrict__ lgp, const float* __restrict__ lgv,
    const float* __restrict__ lbp, const float* __restrict__ lbv)
{
    extern __shared__ __align__(16) uint32_t dsm[];
    __shared__ float2 s_part[8][64];
    __shared__ float2 s_ln[64];

    const int side = blockIdx.y;
    const float* __restrict__ X  = side ? Xv : Xp;
    const float* __restrict__ b1 = side ? b1v : b1p;
    const float* __restrict__ lg = side ? lgv : lgp;
    const float* __restrict__ lb = side ? lbv : lbp;

    const int tid  = threadIdx.x;
    const int lane = tid & 31;
    const int wid  = tid >> 5;
    const int gid  = lane >> 2;
    const int tig  = lane & 3;
    const int wc0  = wid * 32;
    const int row0 = blockIdx.x * 64;
    const uint32_t sdyn = (uint32_t)__cvta_generic_to_shared(dsm);

    float acc[4][4][4];
    #pragma unroll
    for (int mt = 0; mt < 4; mt++)
        #pragma unroll
        for (int nt = 0; nt < 4; nt++)
            #pragma unroll
            for (int e = 0; e < 4; e++) acc[mt][nt][e] = 0.0f;

    const int arow = row0 + (tid >> 2);
    const int acol = (tid & 3) * 4;

    float4 areg;
    // ---- prologue: stages 0 and 1 ----
    areg = *reinterpret_cast<const float4*>(&X[arow * Dd + acol]);
    stsA(dsm, 0, areg, tid);
    cpB(sdyn, 0, side, 0, tid);
    CP_COMMIT();
    areg = *reinterpret_cast<const float4*>(&X[arow * Dd + 16 + acol]);
    stsA(dsm, STG_W, areg, tid);
    cpB(sdyn, STG_W, side, 8, tid);
    CP_COMMIT();
    areg = *reinterpret_cast<const float4*>(&X[arow * Dd + 32 + acol]);
    CP_WAIT1();              // stage 0 ready
    __syncthreads();

    #pragma unroll 1
    for (int kt = 0; kt < 32; kt++) {
        const int cur = (kt % 3) * STG_W;

        if (kt < 30) {
            const int nxt = ((kt + 2) % 3) * STG_W;   // == stage (kt-1), retired
            stsA(dsm, nxt, areg, tid);
            cpB(sdyn, nxt, side, (kt + 2) * 8, tid);
            CP_COMMIT();
            if (kt < 29) {
                int kn = (kt + 3) * 16;
                areg = *reinterpret_cast<const float4*>(&X[arow * Dd + kn + acol]);
            }
        }

        {
            uint32_t ah[4][4], al[4][4], bh[4][2], bl[4][2];
            #pragma unroll
            for (int mt = 0; mt < 4; mt++) {
                int r = mt * 16 + gid;
                ah[mt][0] = dsm[cur + tig * 72 + r];
                ah[mt][1] = dsm[cur + tig * 72 + r + 8];
                ah[mt][2] = dsm[cur + (tig + 4) * 72 + r];
                ah[mt][3] = dsm[cur + (tig + 4) * 72 + r + 8];
                al[mt][0] = dsm[cur + 576 + tig * 72 + r];
                al[mt][1] = dsm[cur + 576 + tig * 72 + r + 8];
                al[mt][2] = dsm[cur + 576 + (tig + 4) * 72 + r];
                al[mt][3] = dsm[cur + 576 + (tig + 4) * 72 + r + 8];
            }
            #pragma unroll
            for (int nt = 0; nt < 4; nt++) {
                int c = wc0 + nt * 8 + gid;
                bh[nt][0] = dsm[cur + 1152 + tig * 264 + c];
                bh[nt][1] = dsm[cur + 1152 + (tig + 4) * 264 + c];
                bl[nt][0] = dsm[cur + 3264 + tig * 264 + c];
                bl[nt][1] = dsm[cur + 3264 + (tig + 4) * 264 + c];
            }
            #pragma unroll
            for (int mt = 0; mt < 4; mt++)
                #pragma unroll
                for (int nt = 0; nt < 4; nt++) {
                    MMA_BF16(acc[mt][nt], ah[mt], bh[nt]);
                    MMA_BF16(acc[mt][nt], al[mt], bh[nt]);
                    MMA_BF16(acc[mt][nt], ah[mt], bl[nt]);
                }
        }

        if (kt < 31) {
            if (kt < 30) CP_WAIT1(); else CP_WAIT0();   // next stage ready
            __syncthreads();
        }
    }

    // ------------- fused epilogue: bias + LayerNorm + GELU + split ----------
    float bcol[8], lgc[8], lbc[8];
    #pragma unroll
    for (int nt = 0; nt < 4; nt++) {
        int c = wc0 + nt * 8 + tig * 2;
        bcol[nt * 2] = __ldg(&b1[c]); bcol[nt * 2 + 1] = __ldg(&b1[c + 1]);
        lgc[nt * 2]  = __ldg(&lg[c]); lgc[nt * 2 + 1]  = __ldg(&lg[c + 1]);
        lbc[nt * 2]  = __ldg(&lb[c]); lbc[nt * 2 + 1]  = __ldg(&lb[c + 1]);
    }

    float s[8], s2[8];
    #pragma unroll
    for (int q = 0; q < 8; q++) { s[q] = 0.0f; s2[q] = 0.0f; }
    #pragma unroll
    for (int mt = 0; mt < 4; mt++)
        #pragma unroll
        for (int nt = 0; nt < 4; nt++)
            #pragma unroll
            for (int e = 0; e < 4; e++) {
                float v = acc[mt][nt][e] + bcol[nt * 2 + (e & 1)];
                acc[mt][nt][e] = v;
                int slot = mt * 2 + (e >> 1);
                s[slot] += v; s2[slot] += v * v;
            }
    #pragma unroll
    for (int q = 0; q < 8; q++) {
        s[q]  += __shfl_xor_sync(0xffffffffu, s[q],  1);
        s[q]  += __shfl_xor_sync(0xffffffffu, s[q],  2);
        s2[q] += __shfl_xor_sync(0xffffffffu, s2[q], 1);
        s2[q] += __shfl_xor_sync(0xffffffffu, s2[q], 2);
    }
    __syncthreads();
    if (tig == 0) {
        #pragma unroll
        for (int mt = 0; mt < 4; mt++) {
            s_part[wid][mt * 16 + gid]     = make_float2(s[mt * 2],     s2[mt * 2]);
            s_part[wid][mt * 16 + 8 + gid] = make_float2(s[mt * 2 + 1], s2[mt * 2 + 1]);
        }
    }
    __syncthreads();
    if (tid < 64) {
        float ts = 0.0f, ts2 = 0.0f;
        #pragma unroll
        for (int w = 0; w < 8; w++) {
            float2 p = s_part[w][tid];
            ts += p.x; ts2 += p.y;
        }
        float mu   = ts * (1.0f / 256.0f);
        float var  = ts2 * (1.0f / 256.0f) - mu * mu;
        s_ln[tid] = make_float2(mu, rsqrtf(var + 1e-5f));
    }
    __syncthreads();

    #pragma unroll
    for (int mt = 0; mt < 4; mt++)
        #pragma unroll
        for (int h = 0; h < 2; h++) {
            int rl = mt * 16 + h * 8 + gid;
            float2 ln = s_ln[rl];
            int row = row0 + rl;
            #pragma unroll
            for (int nt = 0; nt < 4; nt++) {
                float v0 = acc[mt][nt][h * 2];
                float v1 = acc[mt][nt][h * 2 + 1];
                float y0 = gelu_exact((v0 - ln.x) * ln.y * lgc[nt * 2]     + lbc[nt * 2]);
                float y1 = gelu_exact((v1 - ln.x) * ln.y * lgc[nt * 2 + 1] + lbc[nt * 2 + 1]);
                uint32_t hp, lp;
                bf16_split_pack(y0, y1, hp, lp);
                int k2 = (wc0 >> 1) + nt * 4 + tig;
                g_acth[side][row][k2] = hp;
                g_actl[side][row][k2] = lp;
            }
        }
}

// ---------------------------------------------------------------------------
// GEMM2 double-buffered + cp.async: side0 -> mp, side1 -> V (W2v pre-folded).
// BM=128, BN=64, BK=16. 8 warps (4m x 2n), warp tile 32x32.
// ---------------------------------------------------------------------------
#define G2_STG 4224

__device__ __forceinline__ void g2_cp(uint32_t sdyn, int so, int side,
                                      int row0, int k2base, int tid) {
    {
        int row = tid >> 1, quad = tid & 1;
        cp16(sdyn + (uint32_t)(so + row * 12 + quad * 4) * 4,
             &g_acth[side][row0 + row][k2base + quad * 4]);
        cp16(sdyn + (uint32_t)(so + 1536 + row * 12 + quad * 4) * 4,
             &g_actl[side][row0 + row][k2base + quad * 4]);
    }
    {
        int k2l = tid >> 5, r = tid & 31;
        int hl = r >> 4, n4 = r & 15;
        cp16(sdyn + (uint32_t)(so + 3072 + hl * 576 + k2l * 72 + n4 * 4) * 4,
             &g_W2s[side][hl][k2base + k2l][n4 * 4]);
    }
}

__global__ __launch_bounds__(256, 2) void k_gemm2(
    const float* __restrict__ b2p)
{
    __shared__ __align__(16) uint32_t dsm[2 * G2_STG];

    const int side = blockIdx.y;
    const float* __restrict__ b2 = side ? g_b2t : b2p;

    const int tid  = threadIdx.x;
    const int lane = tid & 31;
    const int wid  = tid >> 5;
    const int gid  = lane >> 2;
    const int tig  = lane & 3;
    const int wr0  = (wid & 3) * 32;
    const int wc0  = (wid >> 2) * 32;
    const int row0 = blockIdx.x * 128;
    const uint32_t sdyn = (uint32_t)__cvta_generic_to_shared(dsm);

    float acc[2][4][4];
    #pragma unroll
    for (int mt = 0; mt < 2; mt++)
        #pragma unroll
        for (int nt = 0; nt < 4; nt++)
            #pragma unroll
            for (int e = 0; e < 4; e++) acc[mt][nt][e] = 0.0f;

    g2_cp(sdyn, 0, side, row0, 0, tid);
    CP_COMMIT();
    CP_WAIT0();
    __syncthreads();

    #pragma unroll 1
    for (int kt = 0; kt < 16; kt++) {
        const int cur = (kt & 1) * G2_STG;
        const int nxt = ((kt & 1) ^ 1) * G2_STG;

        if (kt < 15) {
            g2_cp(sdyn, nxt, side, row0, (kt + 1) * 8, tid);
            CP_COMMIT();
        }

        {
            uint32_t ah[2][4], al2[2][4], bh[4][2], bl[4][2];
            #pragma unroll
            for (int mt = 0; mt < 2; mt++) {
                int r = wr0 + mt * 16 + gid;
                ah[mt][0] = dsm[cur + r * 12 + tig];
                ah[mt][1] = dsm[cur + (r + 8) * 12 + tig];
                ah[mt][2] = dsm[cur + r * 12 + tig + 4];
                ah[mt][3] = dsm[cur + (r + 8) * 12 + tig + 4];
                al2[mt][0] = dsm[cur + 1536 + r * 12 + tig];
                al2[mt][1] = dsm[cur + 1536 + (r + 8) * 12 + tig];
                al2[mt][2] = dsm[cur + 1536 + r * 12 + tig + 4];
                al2[mt][3] = dsm[cur + 1536 + (r + 8) * 12 + tig + 4];
            }
            #pragma unroll
            for (int nt = 0; nt < 4; nt++) {
                int c = wc0 + nt * 8 + gid;
                bh[nt][0] = dsm[cur + 3072 + tig * 72 + c];
                bh[nt][1] = dsm[cur + 3072 + (tig + 4) * 72 + c];
                bl[nt][0] = dsm[cur + 3648 + tig * 72 + c];
                bl[nt][1] = dsm[cur + 3648 + (tig + 4) * 72 + c];
            }
            #pragma unroll
            for (int mt = 0; mt < 2; mt++)
                #pragma unroll
                for (int nt = 0; nt < 4; nt++) {
                    MMA_BF16(acc[mt][nt], ah[mt], bh[nt]);
                    MMA_BF16(acc[mt][nt], al2[mt], bh[nt]);
                    MMA_BF16(acc[mt][nt], ah[mt], bl[nt]);
                }
        }

        if (kt < 15) {
            CP_WAIT0();
            __syncthreads();
        }
    }

    #pragma unroll
    for (int mt = 0; mt < 2; mt++)
        #pragma unroll
        for (int nt = 0; nt < 4; nt++) {
            int r = row0 + wr0 + mt * 16 + gid;
            int c = wc0 + nt * 8 + tig * 2;
            float b0 = b2[c], b1b = b2[c + 1];
            float2 v0 = {acc[mt][nt][0] + b0, acc[mt][nt][1] + b1b};
            float2 v1 = {acc[mt][nt][2] + b0, acc[mt][nt][3] + b1b};
            *reinterpret_cast<float2*>(&g_m[side][r][c])     = v0;
            *reinterpret_cast<float2*>(&g_m[side][r + 8][c]) = v1;
        }
}

// ---------------------------------------------------------------------------
// VQ: Q = mp (geometric-product) V; V comes pre-collapsed from gemm2 side1.
// Warp per row; writes packed split Q.
// ---------------------------------------------------------------------------
__global__ __launch_bounds__(256) void k_vq()
{
    __shared__ float s_mp[8][64], s_V[8][64], s_Q[8][64];

    const int tid = threadIdx.x;
    const int lane = tid & 31;
    const int w = tid >> 5;

    const int row = blockIdx.x * 8 + w;

    s_mp[w][lane]      = g_m[0][row][lane];
    s_mp[w][lane + 32] = g_m[0][row][lane + 32];
    s_V[w][lane]       = g_m[1][row][lane];
    s_V[w][lane + 32]  = g_m[1][row][lane + 32];
    __syncwarp();

    const int MASKS_[8] = {0, 1, 2, 4, 3, 5, 6, 7};

    #pragma unroll
    for (int h = 0; h < 2; h++) {
        int f = lane + h * 32;
        int k = f >> 3, jc = f & 7;
        int mjc = MASKS_[jc];
        float q = 0.0f;
        #pragma unroll
        for (int i = 0; i < 8; i++) {
            int mi = MASKS_[i];
            q += s_mp[w][k * 8 + i] * csign(mi, mjc) * s_V[w][k * 8 + (mi ^ mjc)];
        }
        s_Q[w][f] = q;
    }
    __syncwarp();

    uint32_t hp, lp;
    bf16_split_pack(s_Q[w][2 * lane], s_Q[w][2 * lane + 1], hp, lp);
    g_Qh[row][lane] = hp;
    g_Ql[row][lane] = lp;
}

// ---------------------------------------------------------------------------
// READ: out(B,95) = Q(B,64) @ T'(64,95)  (T pre-scaled 1/8), bf16 3x.
// ---------------------------------------------------------------------------
__global__ __launch_bounds__(256, 2) void k_read(float* __restrict__ out)
{
    __shared__ uint32_t Ah[128][20], Al[128][20], Bh[16][136], Bl[16][136];

    const int tid  = threadIdx.x;
    const int lane = tid & 31;
    const int wid  = tid >> 5;
    const int gid  = lane >> 2;
    const int tig  = lane & 3;
    const int wr0  = (wid & 3) * 32;
    const int wc0  = (wid >> 2) * 48;
    const int row0 = blockIdx.x * 128;

    float acc[2][6][4];
    #pragma unroll
    for (int mt = 0; mt < 2; mt++)
        #pragma unroll
        for (int nt = 0; nt < 6; nt++)
            #pragma unroll
            for (int e = 0; e < 4; e++) acc[mt][nt][e] = 0.0f;

    uint4 ahreg[2], alreg[2], bhreg[2], blreg[2];
    #pragma unroll
    for (int q = 0; q < 2; q++) {
        int idx = tid + q * 256;
        int row = idx >> 2, k2q = (idx & 3) * 4;
        ahreg[q] = *reinterpret_cast<const uint4*>(&g_Qh[row0 + row][k2q]);
        alreg[q] = *reinterpret_cast<const uint4*>(&g_Ql[row0 + row][k2q]);
        int k2l = idx >> 5, n4 = (idx & 31) * 4;
        bhreg[q] = *reinterpret_cast<const uint4*>(&g_Th[k2l][n4]);
        blreg[q] = *reinterpret_cast<const uint4*>(&g_Tl[k2l][n4]);
    }

    #pragma unroll 1
    for (int kt = 0; kt < 2; kt++) {
        __syncthreads();
        #pragma unroll
        for (int q = 0; q < 2; q++) {
            int idx = tid + q * 256;
            int row = idx >> 2, k2q = (idx & 3) * 4;
            *reinterpret_cast<uint4*>(&Ah[row][k2q]) = ahreg[q];
            *reinterpret_cast<uint4*>(&Al[row][k2q]) = alreg[q];
            int k2l = idx >> 5, n4 = (idx & 31) * 4;
            *reinterpret_cast<uint4*>(&Bh[k2l][n4]) = bhreg[q];
            *reinterpret_cast<uint4*>(&Bl[k2l][n4]) = blreg[q];
        }
        __syncthreads();

        if (kt == 0) {
            #pragma unroll
            for (int q = 0; q < 2; q++) {
                int idx = tid + q * 256;
                int row = idx >> 2, k2q = (idx & 3) * 4;
                ahreg[q] = *reinterpret_cast<const uint4*>(&g_Qh[row0 + row][16 + k2q]);
                alreg[q] = *reinterpret_cast<const uint4*>(&g_Ql[row0 + row][16 + k2q]);
                int k2l = idx >> 5, n4 = (idx & 31) * 4;
                bhreg[q] = *reinterpret_cast<const uint4*>(&g_Th[16 + k2l][n4]);
                blreg[q] = *reinterpret_cast<const uint4*>(&g_Tl[16 + k2l][n4]);
            }
        }

        #pragma unroll
        for (int k8x = 0; k8x < 16; k8x += 8) {
            uint32_t ah[2][4], al2[2][4], bh[6][2], bl[6][2];
            #pragma unroll
            for (int mt = 0; mt < 2; mt++) {
                int r = wr0 + mt * 16 + gid;
                ah[mt][0] = Ah[r][k8x + tig];     ah[mt][1] = Ah[r + 8][k8x + tig];
                ah[mt][2] = Ah[r][k8x + tig + 4]; ah[mt][3] = Ah[r + 8][k8x + tig + 4];
                al2[mt][0] = Al[r][k8x + tig];     al2[mt][1] = Al[r + 8][k8x + tig];
                al2[mt][2] = Al[r][k8x + tig + 4]; al2[mt][3] = Al[r + 8][k8x + tig + 4];
            }
            #pragma unroll
            for (int nt = 0; nt < 6; nt++) {
                int c = wc0 + nt * 8 + gid;
                bh[nt][0] = Bh[k8x + tig][c]; bh[nt][1] = Bh[k8x + tig + 4][c];
                bl[nt][0] = Bl[k8x + tig][c]; bl[nt][1] = Bl[k8x + tig + 4][c];
            }
            #pragma unroll
            for (int mt = 0; mt < 2; mt++)
                #pragma unroll
                for (int nt = 0; nt < 6; nt++) {
                    MMA_BF16(acc[mt][nt], ah[mt], bh[nt]);
                    MMA_BF16(acc[mt][nt], al2[mt], bh[nt]);
                    MMA_BF16(acc[mt][nt], ah[mt], bl[nt]);
                }
        }
    }

    #pragma unroll
    for (int mt = 0; mt < 2; mt++)
        #pragma unroll
        for (int nt = 0; nt < 6; nt++) {
            int r = row0 + wr0 + mt * 16 + gid;
            int c = wc0 + nt * 8 + tig * 2;
            if (c < Rr)     out[r * Rr + c]             = acc[mt][nt][0];
            if (c + 1 < Rr) out[r * Rr + c + 1]         = acc[mt][nt][1];
            if (c < Rr)     out[(r + 8) * Rr + c]       = acc[mt][nt][2];
            if (c + 1 < Rr) out[(r + 8) * Rr + c + 1]   = acc[mt][nt][3];
        }
}

// ---------------------------------------------------------------------------
extern "C" void kernel_launch(void* const* d_in, const int* in_sizes, int n_in,
                              void* d_out, int out_size)
{
    const float* h_perp = (const float*)d_in[0];
    const float* h_vuln = (const float*)d_in[1];
    const float* Wp1    = (const float*)d_in[2];
    const float* bp1    = (const float*)d_in[3];
    const float* lgp    = (const float*)d_in[4];
    const float* lbp    = (const float*)d_in[5];
    const float* Wp2    = (const float*)d_in[6];
    const float* bp2    = (const float*)d_in[7];
    const float* Wv1    = (const float*)d_in[8];
    const float* bv1    = (const float*)d_in[9];
    const float* lgv    = (const float*)d_in[10];
    const float* lbv    = (const float*)d_in[11];
    const float* Wv2    = (const float*)d_in[12];
    const float* bv2    = (const float*)d_in[13];
    const float* T      = (const float*)d_in[14];
    const float* gw     = (const float*)d_in[15];
    float* out = (float*)d_out;

    cudaFuncSetAttribute(k_gemm1f, cudaFuncAttributeMaxDynamicSharedMemorySize,
                         DSMEM_G1);

    k_prep<<<(N_ALL + 255) / 256, 256>>>(Wp1, Wv1, Wp2, Wv2, T, gw, bv2);
    k_gemm1f<<<dim3(Bsz / 64, 2), 256, DSMEM_G1>>>(h_perp, h_vuln,
        bp1, bv1, lgp, lgv, lbp, lbv);
    k_gemm2<<<dim3(Bsz / 128, 2), 256>>>(bp2);
    k_vq<<<Bsz / 8, 256>>>();
    k_read<<<Bsz / 128, 256>>>(out);
}